// round 2
// baseline (speedup 1.0000x reference)
#include <cuda_runtime.h>

// Problem constants (fixed by the dataset)
#define BB   4
#define LQN  4096
#define LVN  4096
#define CC   384
#define NHH  6
#define NPP  4
#define DHH  64
#define HLV  64
#define WLV  64
#define NROWS (BB*LQN)          // 16384 (also BB*LVN)
#define EPSF 1e-6f

// Scratch (device globals; no allocations allowed)
__device__ float  g_fnorm  [NROWS*CC];
__device__ float  g_qnorm  [NROWS*CC];
__device__ float  g_value  [NROWS*CC];
__device__ float  g_sampled[NROWS*CC];
__device__ float4 g_params [NROWS*NHH*NPP];   // (px, py, attn_w, pad)

// ---------------------------------------------------------------------------
// Kernel 1: LayerNorm for feat (rows [0,16384)) and query (rows [16384,32768))
// 128 threads per row, 3 elements per thread.
// ---------------------------------------------------------------------------
__global__ void __launch_bounds__(128) ln_kernel(
    const float* __restrict__ feat, const float* __restrict__ query,
    const float* __restrict__ fg, const float* __restrict__ fb,
    const float* __restrict__ qg, const float* __restrict__ qb)
{
    int row = blockIdx.x;
    const float* src; float* dst; const float* g; const float* b;
    if (row < NROWS) { src = feat  + (size_t)row*CC;          dst = g_fnorm + (size_t)row*CC;          g = fg; b = fb; }
    else             { int r = row - NROWS;
                       src = query + (size_t)r*CC;            dst = g_qnorm + (size_t)r*CC;            g = qg; b = qb; }

    int tid = threadIdx.x;
    float v[3];
    float s = 0.f, s2 = 0.f;
#pragma unroll
    for (int i = 0; i < 3; i++) {
        v[i] = src[tid + i*128];
        s  += v[i];
        s2 += v[i]*v[i];
    }
#pragma unroll
    for (int off = 16; off > 0; off >>= 1) {
        s  += __shfl_xor_sync(0xffffffffu, s,  off);
        s2 += __shfl_xor_sync(0xffffffffu, s2, off);
    }
    __shared__ float rs[4], rs2[4];
    int w = tid >> 5, l = tid & 31;
    if (l == 0) { rs[w] = s; rs2[w] = s2; }
    __syncthreads();
    s  = rs[0] + rs[1] + rs[2] + rs[3];
    s2 = rs2[0] + rs2[1] + rs2[2] + rs2[3];
    float mu  = s  * (1.f/CC);
    float var = s2 * (1.f/CC) - mu*mu;
    float inv = rsqrtf(var + EPSF);
#pragma unroll
    for (int i = 0; i < 3; i++) {
        int c = tid + i*128;
        dst[c] = (v[i]-mu)*inv*g[c] + b[c];
    }
}

// ---------------------------------------------------------------------------
// Kernel 2/5: SGEMM  C[M=16384, N=384] = A[M,384] @ B[384,384]  (+ epilogue)
//   mode 0: A = g_fnorm,   out = g_value = acc + bias
//   mode 1: A = g_sampled, out = outp    = resid + gamma*(acc + bias)
// Tiles: BM=128, BN=128, BK=16, 256 threads, 8x8 per-thread.
// ---------------------------------------------------------------------------
__global__ void __launch_bounds__(256) sgemm_kernel(
    const float* __restrict__ Bm,   // [384, 384]
    const float* __restrict__ bias, // [384]
    const float* __restrict__ resid,// [M,384] (mode 1)
    const float* __restrict__ gamma,// [384]   (mode 1)
    float* __restrict__ outp,       // (mode 1)
    int mode)
{
    const float* A   = (mode == 0) ? g_fnorm : g_sampled;
    float*       Cm  = (mode == 0) ? g_value : outp;

    __shared__ float As[16][128];
    __shared__ float Bs[16][128];

    int tid = threadIdx.x;
    int colBase = blockIdx.x * 128;
    int rowBase = blockIdx.y * 128;

    int ty = tid >> 4, tx = tid & 15;

    // A-load mapping: 128 rows x 16 cols per chunk; float4 per thread x2
    int lr = tid >> 2;          // 0..63
    int lc = (tid & 3) * 4;     // 0,4,8,12
    // B-load mapping: 16 rows x 128 cols; float4 per thread x2
    int br = tid >> 5;          // 0..7
    int bc = (tid & 31) * 4;    // 0..124

    float acc[8][8];
#pragma unroll
    for (int i = 0; i < 8; i++)
#pragma unroll
        for (int j = 0; j < 8; j++) acc[i][j] = 0.f;

    for (int kb = 0; kb < CC; kb += 16) {
#pragma unroll
        for (int i = 0; i < 2; i++) {
            float4 a = *(const float4*)(A + (size_t)(rowBase + lr + i*64)*CC + kb + lc);
            As[lc+0][lr + i*64] = a.x;
            As[lc+1][lr + i*64] = a.y;
            As[lc+2][lr + i*64] = a.z;
            As[lc+3][lr + i*64] = a.w;
        }
#pragma unroll
        for (int i = 0; i < 2; i++) {
            float4 bv4 = *(const float4*)(Bm + (size_t)(kb + br + i*8)*CC + colBase + bc);
            *(float4*)&Bs[br + i*8][bc] = bv4;
        }
        __syncthreads();

#pragma unroll
        for (int k = 0; k < 16; k++) {
            float af[8], bf[8];
            *(float4*)&af[0] = *(const float4*)&As[k][ty*8];
            *(float4*)&af[4] = *(const float4*)&As[k][ty*8 + 4];
            *(float4*)&bf[0] = *(const float4*)&Bs[k][tx*8];
            *(float4*)&bf[4] = *(const float4*)&Bs[k][tx*8 + 4];
#pragma unroll
            for (int i = 0; i < 8; i++)
#pragma unroll
                for (int j = 0; j < 8; j++)
                    acc[i][j] = fmaf(af[i], bf[j], acc[i][j]);
        }
        __syncthreads();
    }

#pragma unroll
    for (int i = 0; i < 8; i++) {
        int row = rowBase + ty*8 + i;
#pragma unroll
        for (int j = 0; j < 8; j++) {
            int col = colBase + tx*8 + j;
            float v = acc[i][j] + bias[col];
            if (mode == 1)
                v = resid[(size_t)row*CC + col] + gamma[col]*v;
            Cm[(size_t)row*CC + col] = v;
        }
    }
}

// ---------------------------------------------------------------------------
// Kernel 3: sampling params.
//   raw72 = q_norm @ [Wo | Wa] + [bo | ba]   (N=72 small GEMM, 32 queries/blk)
//   then softmax over 4 points per head and convert to pixel coords:
//   px = ref_x*64 + off_x - 0.5 ; py = ref_y*64 + off_y - 0.5
// 288 threads: c = tid%72, row-group rg = tid/72 (8 rows each).
// ---------------------------------------------------------------------------
__global__ void __launch_bounds__(288) params_kernel(
    const float* __restrict__ Wo, const float* __restrict__ Wa,
    const float* __restrict__ bo, const float* __restrict__ ba,
    const float* __restrict__ refp)
{
    __shared__ float Qs[32][16];
    __shared__ float Ws[16][72];
    __shared__ float S [32][73];

    int tid   = threadIdx.x;
    int qBase = blockIdx.x * 32;
    int c  = tid % 72;
    int rg = tid / 72;          // 0..3

    float acc[8];
#pragma unroll
    for (int i = 0; i < 8; i++) acc[i] = 0.f;

    for (int kb = 0; kb < CC; kb += 16) {
        if (tid < 256) {
#pragma unroll
            for (int i = 0; i < 2; i++) {
                int idx = tid + i*256;
                int r = idx >> 4, k = idx & 15;
                Qs[r][k] = g_qnorm[(size_t)(qBase + r)*CC + kb + k];
            }
        }
#pragma unroll
        for (int i = 0; i < 4; i++) {
            int idx = tid + i*288;          // 0..1151 = 16*72
            int k  = idx / 72;
            int cc = idx % 72;
            Ws[k][cc] = (cc < 48) ? Wo[(size_t)(kb + k)*48 + cc]
                                  : Wa[(size_t)(kb + k)*24 + cc - 48];
        }
        __syncthreads();
#pragma unroll
        for (int k = 0; k < 16; k++) {
            float bval = Ws[k][c];
#pragma unroll
            for (int i = 0; i < 8; i++)
                acc[i] = fmaf(Qs[rg*8 + i][k], bval, acc[i]);
        }
        __syncthreads();
    }

    float bias = (c < 48) ? bo[c] : ba[c - 48];
#pragma unroll
    for (int i = 0; i < 8; i++) S[rg*8 + i][c] = acc[i] + bias;
    __syncthreads();

    if (tid < 192) {
        int q = tid / 6, h = tid % 6;
        int gq = qBase + q;
        float rx = refp[(size_t)gq*2 + 0] * (float)WLV;
        float ry = refp[(size_t)gq*2 + 1] * (float)HLV;
        float a0 = S[q][48 + h*4 + 0];
        float a1 = S[q][48 + h*4 + 1];
        float a2 = S[q][48 + h*4 + 2];
        float a3 = S[q][48 + h*4 + 3];
        float m  = fmaxf(fmaxf(a0, a1), fmaxf(a2, a3));
        float e0 = expf(a0 - m), e1 = expf(a1 - m), e2 = expf(a2 - m), e3 = expf(a3 - m);
        float inv = 1.f / (e0 + e1 + e2 + e3);
        float ws[4] = {e0*inv, e1*inv, e2*inv, e3*inv};
#pragma unroll
        for (int p = 0; p < 4; p++) {
            float px = rx + S[q][h*8 + 2*p + 0] - 0.5f;
            float py = ry + S[q][h*8 + 2*p + 1] - 0.5f;
            g_params[(size_t)(gq*NHH + h)*NPP + p] = make_float4(px, py, ws[p], 0.f);
        }
    }
}

// ---------------------------------------------------------------------------
// Kernel 4: bilinear deformable sampling.
// One block per (b,q): 384 threads, h = tid/64, d = tid%64.
// Out-of-bounds corners contribute 0 (matches reference valid-mask semantics).
// ---------------------------------------------------------------------------
__global__ void __launch_bounds__(384) sample_kernel()
{
    int gq = blockIdx.x;
    int b  = gq >> 12;     // LQN = 4096
    int tid = threadIdx.x;

    __shared__ float4 prm[NHH*NPP];
    if (tid < NHH*NPP) prm[tid] = g_params[(size_t)gq*NHH*NPP + tid];
    __syncthreads();

    int h = tid >> 6, d = tid & 63;
    const float* vb = g_value + (size_t)b*LVN*CC + h*DHH + d;

    float acc = 0.f;
#pragma unroll
    for (int p = 0; p < 4; p++) {
        float4 pr = prm[h*NPP + p];
        float x0f = floorf(pr.x), y0f = floorf(pr.y);
        float fx = pr.x - x0f, fy = pr.y - y0f;
        int ix = (int)x0f, iy = (int)y0f;
        float w00 = (1.f-fx)*(1.f-fy)*pr.z;
        float w10 = fx*(1.f-fy)*pr.z;
        float w01 = (1.f-fx)*fy*pr.z;
        float w11 = fx*fy*pr.z;
        bool xv0 = (ix   >= 0) && (ix   < WLV);
        bool xv1 = (ix+1 >= 0) && (ix+1 < WLV);
        if (iy >= 0 && iy < HLV) {
            size_t base = (size_t)iy*WLV*CC;
            if (xv0) acc = fmaf(w00, vb[base + (size_t)ix    *CC], acc);
            if (xv1) acc = fmaf(w10, vb[base + (size_t)(ix+1)*CC], acc);
        }
        if (iy+1 >= 0 && iy+1 < HLV) {
            size_t base = (size_t)(iy+1)*WLV*CC;
            if (xv0) acc = fmaf(w01, vb[base + (size_t)ix    *CC], acc);
            if (xv1) acc = fmaf(w11, vb[base + (size_t)(ix+1)*CC], acc);
        }
    }
    g_sampled[(size_t)gq*CC + tid] = acc;
}

// ---------------------------------------------------------------------------
extern "C" void kernel_launch(void* const* d_in, const int* in_sizes, int n_in,
                              void* d_out, int out_size)
{
    const float* query = (const float*)d_in[0];
    const float* refp  = (const float*)d_in[1];
    const float* feat  = (const float*)d_in[2];
    // d_in[3]: spatial_shapes (int32, fixed [[64,64]]), d_in[4]: level_start_index
    const float* ln_q_g = (const float*)d_in[5];
    const float* ln_q_b = (const float*)d_in[6];
    const float* ln_f_g = (const float*)d_in[7];
    const float* ln_f_b = (const float*)d_in[8];
    const float* gamma  = (const float*)d_in[9];
    const float* Wv   = (const float*)d_in[10];
    const float* bv   = (const float*)d_in[11];
    const float* Wo   = (const float*)d_in[12];
    const float* bo   = (const float*)d_in[13];
    const float* Wa   = (const float*)d_in[14];
    const float* ba   = (const float*)d_in[15];
    const float* Wout = (const float*)d_in[16];
    const float* bout = (const float*)d_in[17];
    float* out = (float*)d_out;

    // 1. LayerNorms (feat + query)
    ln_kernel<<<2*NROWS, 128>>>(feat, query, ln_f_g, ln_f_b, ln_q_g, ln_q_b);

    // 2. value = f_norm @ Wv + bv
    sgemm_kernel<<<dim3(CC/128, NROWS/128), 256>>>(Wv, bv, nullptr, nullptr, nullptr, 0);

    // 3. sampling params (offsets + softmax attn weights)
    params_kernel<<<NROWS/32, 288>>>(Wo, Wa, bo, ba, refp);

    // 4. bilinear sampling
    sample_kernel<<<NROWS, 384>>>();

    // 5. out = query + gamma * (sampled @ Wout + bout)
    sgemm_kernel<<<dim3(CC/128, NROWS/128), 256>>>(Wout, bout, query, gamma, out, 1);
}

// round 3
// speedup vs baseline: 2.4134x; 2.4134x over previous
#include <cuda_runtime.h>
#include <cuda_bf16.h>
#include <cstdint>

// Problem constants (fixed by the dataset)
#define BB   4
#define LQN  4096
#define LVN  4096
#define CC   384
#define NHH  6
#define NPP  4
#define DHH  64
#define HLV  64
#define WLV  64
#define NROWS (BB*LQN)          // 16384
#define EPSF 1e-6f

// GEMM tiling
#define BM 128
#define BN 128
#define BKK 64
#define AS_STRIDE 72            // 64 + 8 pad (bf16 elems)
#define BS_STRIDE 136           // 128 + 8 pad

// Scratch (device globals; no allocations allowed)
__device__ __nv_bfloat16 g_fnorm  [NROWS*CC];
__device__ float         g_qnorm  [NROWS*CC];
__device__ __nv_bfloat16 g_value  [NROWS*CC];
__device__ __nv_bfloat16 g_sampled[NROWS*CC];
__device__ float4        g_params [NROWS*NHH*NPP];   // (px, py, attn_w, pad)
__device__ __nv_bfloat16 g_Wv_bf  [CC*CC];
__device__ __nv_bfloat16 g_Wout_bf[CC*CC];

// ---------------------------------------------------------------------------
// PTX helpers
// ---------------------------------------------------------------------------
__device__ __forceinline__ void ldm_x4(uint32_t &r0, uint32_t &r1, uint32_t &r2, uint32_t &r3, uint32_t addr)
{
    asm volatile("ldmatrix.sync.aligned.m8n8.x4.shared.b16 {%0,%1,%2,%3}, [%4];\n"
                 : "=r"(r0), "=r"(r1), "=r"(r2), "=r"(r3) : "r"(addr));
}
__device__ __forceinline__ void ldm_x4_trans(uint32_t &r0, uint32_t &r1, uint32_t &r2, uint32_t &r3, uint32_t addr)
{
    asm volatile("ldmatrix.sync.aligned.m8n8.x4.trans.shared.b16 {%0,%1,%2,%3}, [%4];\n"
                 : "=r"(r0), "=r"(r1), "=r"(r2), "=r"(r3) : "r"(addr));
}
__device__ __forceinline__ void mma_bf16(float* c, const uint32_t* a, uint32_t b0, uint32_t b1)
{
    asm volatile(
        "mma.sync.aligned.m16n8k16.row.col.f32.bf16.bf16.f32 "
        "{%0,%1,%2,%3}, {%4,%5,%6,%7}, {%8,%9}, {%0,%1,%2,%3};\n"
        : "+f"(c[0]), "+f"(c[1]), "+f"(c[2]), "+f"(c[3])
        : "r"(a[0]), "r"(a[1]), "r"(a[2]), "r"(a[3]), "r"(b0), "r"(b1));
}

// ---------------------------------------------------------------------------
// Kernel 0: convert weights fp32 -> bf16
// ---------------------------------------------------------------------------
__global__ void __launch_bounds__(256) convert_w_kernel(
    const float* __restrict__ Wv, const float* __restrict__ Wout)
{
    int i = blockIdx.x * 256 + threadIdx.x;
    if (i < CC*CC) {
        g_Wv_bf[i]   = __float2bfloat16(Wv[i]);
        g_Wout_bf[i] = __float2bfloat16(Wout[i]);
    }
}

// ---------------------------------------------------------------------------
// Kernel 1: LayerNorm. feat rows -> g_fnorm (bf16), query rows -> g_qnorm (f32)
// ---------------------------------------------------------------------------
__global__ void __launch_bounds__(128) ln_kernel(
    const float* __restrict__ feat, const float* __restrict__ query,
    const float* __restrict__ fg, const float* __restrict__ fb,
    const float* __restrict__ qg, const float* __restrict__ qb)
{
    int row = blockIdx.x;
    bool isFeat = row < NROWS;
    const float* src = isFeat ? feat + (size_t)row*CC : query + (size_t)(row - NROWS)*CC;
    const float* g = isFeat ? fg : qg;
    const float* b = isFeat ? fb : qb;

    int tid = threadIdx.x;
    float v[3];
    float s = 0.f, s2 = 0.f;
#pragma unroll
    for (int i = 0; i < 3; i++) {
        v[i] = src[tid + i*128];
        s  += v[i];
        s2 += v[i]*v[i];
    }
#pragma unroll
    for (int off = 16; off > 0; off >>= 1) {
        s  += __shfl_xor_sync(0xffffffffu, s,  off);
        s2 += __shfl_xor_sync(0xffffffffu, s2, off);
    }
    __shared__ float rs[4], rs2[4];
    int w = tid >> 5, l = tid & 31;
    if (l == 0) { rs[w] = s; rs2[w] = s2; }
    __syncthreads();
    s  = rs[0] + rs[1] + rs[2] + rs[3];
    s2 = rs2[0] + rs2[1] + rs2[2] + rs2[3];
    float mu  = s  * (1.f/CC);
    float var = s2 * (1.f/CC) - mu*mu;
    float inv = rsqrtf(var + EPSF);
    if (isFeat) {
        __nv_bfloat16* dst = g_fnorm + (size_t)row*CC;
#pragma unroll
        for (int i = 0; i < 3; i++) {
            int c = tid + i*128;
            dst[c] = __float2bfloat16((v[i]-mu)*inv*g[c] + b[c]);
        }
    } else {
        float* dst = g_qnorm + (size_t)(row - NROWS)*CC;
#pragma unroll
        for (int i = 0; i < 3; i++) {
            int c = tid + i*128;
            dst[c] = (v[i]-mu)*inv*g[c] + b[c];
        }
    }
}

// ---------------------------------------------------------------------------
// Kernel 2/5: bf16 tensor-core GEMM  C[16384,384] = A[16384,384] @ W[384,384]
//   MODE 0: A = g_fnorm,   out = g_value (bf16) = acc + bias
//   MODE 1: A = g_sampled, out = outF (f32)     = resid + gamma*(acc + bias)
// 256 threads = 8 warps (4 m x 2 n), warp tile 32x64, BK=64.
// ---------------------------------------------------------------------------
template<int MODE>
__global__ void __launch_bounds__(256) mma_gemm_kernel(
    const __nv_bfloat16* __restrict__ A,
    const __nv_bfloat16* __restrict__ Bw,
    const float* __restrict__ bias,
    const float* __restrict__ resid,
    const float* __restrict__ gamma,
    float* __restrict__ outF)
{
    __shared__ __nv_bfloat16 As[BM*AS_STRIDE];
    __shared__ __nv_bfloat16 Bs[BKK*BS_STRIDE];

    int tid  = threadIdx.x;
    int warp = tid >> 5, lane = tid & 31;
    int wm = warp >> 1, wn = warp & 1;
    int rowBase = blockIdx.y * BM;
    int colBase = blockIdx.x * BN;

    float acc[2][8][4];
#pragma unroll
    for (int i = 0; i < 2; i++)
#pragma unroll
        for (int j = 0; j < 8; j++)
#pragma unroll
            for (int k = 0; k < 4; k++) acc[i][j][k] = 0.f;

    // precomputed ldmatrix lane geometry
    int a_mrow = (lane & 7) + ((lane >> 3) & 1) * 8;   // + mf*16 + wm*32
    int a_kcol = (lane >> 4) * 8;                       // + k0
    int b_krow = (lane & 7) + ((lane >> 3) & 1) * 8;   // + k0
    int b_ncol = (lane >> 4) * 8;                       // + nf4*16 + wn*64

    for (int kb = 0; kb < CC; kb += BKK) {
        // Load A tile: 128 x 64 bf16 = 1024 uint4
#pragma unroll
        for (int i = 0; i < 4; i++) {
            int idx = tid + i*256;
            int r = idx >> 3, c = (idx & 7) * 8;
            *(uint4*)&As[r*AS_STRIDE + c] =
                *(const uint4*)(A + (size_t)(rowBase + r)*CC + kb + c);
        }
        // Load B tile: 64 x 128 bf16 = 1024 uint4
#pragma unroll
        for (int i = 0; i < 4; i++) {
            int idx = tid + i*256;
            int r = idx >> 4, c = (idx & 15) * 8;
            *(uint4*)&Bs[r*BS_STRIDE + c] =
                *(const uint4*)(Bw + (size_t)(kb + r)*CC + colBase + c);
        }
        __syncthreads();

#pragma unroll
        for (int ks = 0; ks < 4; ks++) {
            int k0 = ks * 16;
            uint32_t a[2][4];
#pragma unroll
            for (int mf = 0; mf < 2; mf++) {
                int mrow = wm*32 + mf*16 + a_mrow;
                uint32_t addr = (uint32_t)__cvta_generic_to_shared(
                    &As[mrow*AS_STRIDE + k0 + a_kcol]);
                ldm_x4(a[mf][0], a[mf][1], a[mf][2], a[mf][3], addr);
            }
#pragma unroll
            for (int nf4 = 0; nf4 < 4; nf4++) {
                int krow = k0 + b_krow;
                int ncol = wn*64 + nf4*16 + b_ncol;
                uint32_t addr = (uint32_t)__cvta_generic_to_shared(
                    &Bs[krow*BS_STRIDE + ncol]);
                uint32_t b0, b1, b2, b3;
                ldm_x4_trans(b0, b1, b2, b3, addr);
#pragma unroll
                for (int mf = 0; mf < 2; mf++) {
                    mma_bf16(acc[mf][nf4*2 + 0], a[mf], b0, b1);
                    mma_bf16(acc[mf][nf4*2 + 1], a[mf], b2, b3);
                }
            }
        }
        __syncthreads();
    }

    // Epilogue. c-frag: c0:(r,c) c1:(r,c+1) c2:(r+8,c) c3:(r+8,c+1),
    // r = lane>>2, c = (lane&3)*2
    int lrow = lane >> 2;
    int lcol = (lane & 3) * 2;
#pragma unroll
    for (int mf = 0; mf < 2; mf++) {
#pragma unroll
        for (int nf = 0; nf < 8; nf++) {
            int col = colBase + wn*64 + nf*8 + lcol;
            float bx = bias[col], by = bias[col + 1];
#pragma unroll
            for (int half = 0; half < 2; half++) {
                int row = rowBase + wm*32 + mf*16 + lrow + half*8;
                float vx = acc[mf][nf][half*2 + 0] + bx;
                float vy = acc[mf][nf][half*2 + 1] + by;
                if (MODE == 0) {
                    __nv_bfloat162 o;
                    o.x = __float2bfloat16(vx);
                    o.y = __float2bfloat16(vy);
                    *(__nv_bfloat162*)&g_value[(size_t)row*CC + col] = o;
                } else {
                    const float2 rd = *(const float2*)&resid[(size_t)row*CC + col];
                    float2 o;
                    o.x = rd.x + gamma[col]   * vx;
                    o.y = rd.y + gamma[col+1] * vy;
                    *(float2*)&outF[(size_t)row*CC + col] = o;
                }
            }
        }
    }
}

// ---------------------------------------------------------------------------
// Kernel 3: sampling params (q@[Wo|Wa] + softmax + pixel coords)  [unchanged]
// ---------------------------------------------------------------------------
__global__ void __launch_bounds__(288) params_kernel(
    const float* __restrict__ Wo, const float* __restrict__ Wa,
    const float* __restrict__ bo, const float* __restrict__ ba,
    const float* __restrict__ refp)
{
    __shared__ float Qs[32][16];
    __shared__ float Ws[16][72];
    __shared__ float S [32][73];

    int tid   = threadIdx.x;
    int qBase = blockIdx.x * 32;
    int c  = tid % 72;
    int rg = tid / 72;

    float acc[8];
#pragma unroll
    for (int i = 0; i < 8; i++) acc[i] = 0.f;

    for (int kb = 0; kb < CC; kb += 16) {
        if (tid < 256) {
#pragma unroll
            for (int i = 0; i < 2; i++) {
                int idx = tid + i*256;
                int r = idx >> 4, k = idx & 15;
                Qs[r][k] = g_qnorm[(size_t)(qBase + r)*CC + kb + k];
            }
        }
#pragma unroll
        for (int i = 0; i < 4; i++) {
            int idx = tid + i*288;
            int k  = idx / 72;
            int cc = idx % 72;
            Ws[k][cc] = (cc < 48) ? Wo[(size_t)(kb + k)*48 + cc]
                                  : Wa[(size_t)(kb + k)*24 + cc - 48];
        }
        __syncthreads();
#pragma unroll
        for (int k = 0; k < 16; k++) {
            float bval = Ws[k][c];
#pragma unroll
            for (int i = 0; i < 8; i++)
                acc[i] = fmaf(Qs[rg*8 + i][k], bval, acc[i]);
        }
        __syncthreads();
    }

    float bias = (c < 48) ? bo[c] : ba[c - 48];
#pragma unroll
    for (int i = 0; i < 8; i++) S[rg*8 + i][c] = acc[i] + bias;
    __syncthreads();

    if (tid < 192) {
        int q = tid / 6, h = tid % 6;
        int gq = qBase + q;
        float rx = refp[(size_t)gq*2 + 0] * (float)WLV;
        float ry = refp[(size_t)gq*2 + 1] * (float)HLV;
        float a0 = S[q][48 + h*4 + 0];
        float a1 = S[q][48 + h*4 + 1];
        float a2 = S[q][48 + h*4 + 2];
        float a3 = S[q][48 + h*4 + 3];
        float m  = fmaxf(fmaxf(a0, a1), fmaxf(a2, a3));
        float e0 = expf(a0 - m), e1 = expf(a1 - m), e2 = expf(a2 - m), e3 = expf(a3 - m);
        float inv = 1.f / (e0 + e1 + e2 + e3);
        float ws[4] = {e0*inv, e1*inv, e2*inv, e3*inv};
#pragma unroll
        for (int p = 0; p < 4; p++) {
            float px = rx + S[q][h*8 + 2*p + 0] - 0.5f;
            float py = ry + S[q][h*8 + 2*p + 1] - 0.5f;
            g_params[(size_t)(gq*NHH + h)*NPP + p] = make_float4(px, py, ws[p], 0.f);
        }
    }
}

// ---------------------------------------------------------------------------
// Kernel 4: bilinear deformable sampling (bf16 value, bf16 out).
// 2 queries per block; per query 192 threads: h = t/32, channel pair = t%32.
// ---------------------------------------------------------------------------
__global__ void __launch_bounds__(384) sample_kernel()
{
    int blk = blockIdx.x;            // 8192 blocks
    int tid = threadIdx.x;
    int sub = tid / 192;
    int t   = tid % 192;
    int gq  = blk*2 + sub;
    int b   = gq >> 12;              // LQN = 4096

    __shared__ float4 prm[2][NHH*NPP];
    if (tid < 2*NHH*NPP)
        prm[tid / 24][tid % 24] = g_params[(size_t)(blk*2)*24 + tid];
    __syncthreads();

    int h  = t >> 5;                 // 0..5
    int dp = t & 31;                 // channel pair 0..31
    const __nv_bfloat16* vb = g_value + (size_t)b*LVN*CC + h*DHH + dp*2;

    float ax = 0.f, ay = 0.f;
#pragma unroll
    for (int p = 0; p < 4; p++) {
        float4 pr = prm[sub][h*NPP + p];
        float x0f = floorf(pr.x), y0f = floorf(pr.y);
        float fx = pr.x - x0f, fy = pr.y - y0f;
        int ix = (int)x0f, iy = (int)y0f;
        float w00 = (1.f-fx)*(1.f-fy)*pr.z;
        float w10 = fx*(1.f-fy)*pr.z;
        float w01 = (1.f-fx)*fy*pr.z;
        float w11 = fx*fy*pr.z;
        bool xv0 = (ix   >= 0) && (ix   < WLV);
        bool xv1 = (ix+1 >= 0) && (ix+1 < WLV);
        if (iy >= 0 && iy < HLV) {
            size_t base = (size_t)iy*WLV*CC;
            if (xv0) {
                float2 f = __bfloat1622float2(*(const __nv_bfloat162*)(vb + base + (size_t)ix*CC));
                ax = fmaf(w00, f.x, ax); ay = fmaf(w00, f.y, ay);
            }
            if (xv1) {
                float2 f = __bfloat1622float2(*(const __nv_bfloat162*)(vb + base + (size_t)(ix+1)*CC));
                ax = fmaf(w10, f.x, ax); ay = fmaf(w10, f.y, ay);
            }
        }
        if (iy+1 >= 0 && iy+1 < HLV) {
            size_t base = (size_t)(iy+1)*WLV*CC;
            if (xv0) {
                float2 f = __bfloat1622float2(*(const __nv_bfloat162*)(vb + base + (size_t)ix*CC));
                ax = fmaf(w01, f.x, ax); ay = fmaf(w01, f.y, ay);
            }
            if (xv1) {
                float2 f = __bfloat1622float2(*(const __nv_bfloat162*)(vb + base + (size_t)(ix+1)*CC));
                ax = fmaf(w11, f.x, ax); ay = fmaf(w11, f.y, ay);
            }
        }
    }
    __nv_bfloat162 o;
    o.x = __float2bfloat16(ax);
    o.y = __float2bfloat16(ay);
    *(__nv_bfloat162*)&g_sampled[(size_t)gq*CC + h*DHH + dp*2] = o;
}

// ---------------------------------------------------------------------------
extern "C" void kernel_launch(void* const* d_in, const int* in_sizes, int n_in,
                              void* d_out, int out_size)
{
    const float* query = (const float*)d_in[0];
    const float* refp  = (const float*)d_in[1];
    const float* feat  = (const float*)d_in[2];
    const float* ln_q_g = (const float*)d_in[5];
    const float* ln_q_b = (const float*)d_in[6];
    const float* ln_f_g = (const float*)d_in[7];
    const float* ln_f_b = (const float*)d_in[8];
    const float* gamma  = (const float*)d_in[9];
    const float* Wv   = (const float*)d_in[10];
    const float* bv   = (const float*)d_in[11];
    const float* Wo   = (const float*)d_in[12];
    const float* bo   = (const float*)d_in[13];
    const float* Wa   = (const float*)d_in[14];
    const float* ba   = (const float*)d_in[15];
    const float* Wout = (const float*)d_in[16];
    const float* bout = (const float*)d_in[17];
    float* out = (float*)d_out;

    // device-global pointers for kernel args
    __nv_bfloat16 *p_fnorm, *p_sampled, *p_Wv, *p_Wout;
    cudaGetSymbolAddress((void**)&p_fnorm,   g_fnorm);
    cudaGetSymbolAddress((void**)&p_sampled, g_sampled);
    cudaGetSymbolAddress((void**)&p_Wv,      g_Wv_bf);
    cudaGetSymbolAddress((void**)&p_Wout,    g_Wout_bf);

    // 0. weights -> bf16
    convert_w_kernel<<<(CC*CC + 255)/256, 256>>>(Wv, Wout);

    // 1. LayerNorms (feat -> bf16, query -> f32)
    ln_kernel<<<2*NROWS, 128>>>(feat, query, ln_f_g, ln_f_b, ln_q_g, ln_q_b);

    // 2. value = f_norm @ Wv + bv   (bf16 out)
    mma_gemm_kernel<0><<<dim3(CC/BN, NROWS/BM), 256>>>(
        p_fnorm, p_Wv, bv, nullptr, nullptr, nullptr);

    // 3. sampling params
    params_kernel<<<NROWS/32, 288>>>(Wo, Wa, bo, ba, refp);

    // 4. bilinear sampling (bf16 in/out)
    sample_kernel<<<NROWS/2, 384>>>();

    // 5. out = query + gamma * (sampled @ Wout + bout)
    mma_gemm_kernel<1><<<dim3(CC/BN, NROWS/BM), 256>>>(
        p_sampled, p_Wout, bout, query, gamma, out);
}

// round 4
// speedup vs baseline: 3.4142x; 1.4147x over previous
#include <cuda_runtime.h>
#include <cuda_bf16.h>
#include <cstdint>

// Problem constants (fixed by the dataset)
#define BB   4
#define LQN  4096
#define LVN  4096
#define CC   384
#define NHH  6
#define NPP  4
#define DHH  64
#define HLV  64
#define WLV  64
#define NROWS (BB*LQN)          // 16384
#define EPSF 1e-6f

// Big-GEMM tiling
#define BM 128
#define BN 128
#define BKK 64
#define AS_STRIDE 72            // 64 + 8 pad (bf16 elems)
#define BS_STRIDE 136           // 128 + 8 pad

// Params-GEMM tiling
#define PBM 64
#define PBN 80                  // 72 used + 8 zero-pad
#define PW_STRIDE 88            // 80 + 8 pad

// Scratch (device globals; no allocations allowed)
__device__ __nv_bfloat16 g_fnorm  [NROWS*CC];
__device__ __nv_bfloat16 g_qnorm  [NROWS*CC];
__device__ __nv_bfloat16 g_value  [NROWS*CC];
__device__ __nv_bfloat16 g_sampled[NROWS*CC];
__device__ float4        g_params [NROWS*NHH*NPP];   // (px, py, attn_w, pad)
__device__ __nv_bfloat16 g_Wv_bf  [CC*CC];
__device__ __nv_bfloat16 g_Wout_bf[CC*CC];
__device__ __nv_bfloat16 g_W72    [CC*PBN];          // [384][80]: Wo|Wa|0

// ---------------------------------------------------------------------------
// PTX helpers
// ---------------------------------------------------------------------------
__device__ __forceinline__ void ldm_x4(uint32_t &r0, uint32_t &r1, uint32_t &r2, uint32_t &r3, uint32_t addr)
{
    asm volatile("ldmatrix.sync.aligned.m8n8.x4.shared.b16 {%0,%1,%2,%3}, [%4];\n"
                 : "=r"(r0), "=r"(r1), "=r"(r2), "=r"(r3) : "r"(addr));
}
__device__ __forceinline__ void ldm_x4_trans(uint32_t &r0, uint32_t &r1, uint32_t &r2, uint32_t &r3, uint32_t addr)
{
    asm volatile("ldmatrix.sync.aligned.m8n8.x4.trans.shared.b16 {%0,%1,%2,%3}, [%4];\n"
                 : "=r"(r0), "=r"(r1), "=r"(r2), "=r"(r3) : "r"(addr));
}
__device__ __forceinline__ void mma_bf16(float* c, const uint32_t* a, uint32_t b0, uint32_t b1)
{
    asm volatile(
        "mma.sync.aligned.m16n8k16.row.col.f32.bf16.bf16.f32 "
        "{%0,%1,%2,%3}, {%4,%5,%6,%7}, {%8,%9}, {%0,%1,%2,%3};\n"
        : "+f"(c[0]), "+f"(c[1]), "+f"(c[2]), "+f"(c[3])
        : "r"(a[0]), "r"(a[1]), "r"(a[2]), "r"(a[3]), "r"(b0), "r"(b1));
}

// ---------------------------------------------------------------------------
// Kernel 0: convert weights fp32 -> bf16 (Wv, Wout, packed [Wo|Wa|0])
// ---------------------------------------------------------------------------
__global__ void __launch_bounds__(256) convert_w_kernel(
    const float* __restrict__ Wv, const float* __restrict__ Wout,
    const float* __restrict__ Wo, const float* __restrict__ Wa)
{
    int i = blockIdx.x * 256 + threadIdx.x;
    if (i < CC*CC) {
        g_Wv_bf[i]   = __float2bfloat16(Wv[i]);
        g_Wout_bf[i] = __float2bfloat16(Wout[i]);
    }
    if (i < CC*PBN) {
        int r = i / PBN, c = i % PBN;
        float v = (c < 48) ? Wo[r*48 + c] : (c < 72 ? Wa[r*24 + c - 48] : 0.f);
        g_W72[i] = __float2bfloat16(v);
    }
}

// ---------------------------------------------------------------------------
// Kernel 1: LayerNorm. feat -> g_fnorm (bf16), query -> g_qnorm (bf16)
// ---------------------------------------------------------------------------
__global__ void __launch_bounds__(128) ln_kernel(
    const float* __restrict__ feat, const float* __restrict__ query,
    const float* __restrict__ fg, const float* __restrict__ fb,
    const float* __restrict__ qg, const float* __restrict__ qb)
{
    int row = blockIdx.x;
    bool isFeat = row < NROWS;
    const float* src = isFeat ? feat + (size_t)row*CC : query + (size_t)(row - NROWS)*CC;
    const float* g = isFeat ? fg : qg;
    const float* b = isFeat ? fb : qb;
    __nv_bfloat16* dst = isFeat ? g_fnorm + (size_t)row*CC
                                : g_qnorm + (size_t)(row - NROWS)*CC;

    int tid = threadIdx.x;
    float v[3];
    float s = 0.f, s2 = 0.f;
#pragma unroll
    for (int i = 0; i < 3; i++) {
        v[i] = src[tid + i*128];
        s  += v[i];
        s2 += v[i]*v[i];
    }
#pragma unroll
    for (int off = 16; off > 0; off >>= 1) {
        s  += __shfl_xor_sync(0xffffffffu, s,  off);
        s2 += __shfl_xor_sync(0xffffffffu, s2, off);
    }
    __shared__ float rs[4], rs2[4];
    int w = tid >> 5, l = tid & 31;
    if (l == 0) { rs[w] = s; rs2[w] = s2; }
    __syncthreads();
    s  = rs[0] + rs[1] + rs[2] + rs[3];
    s2 = rs2[0] + rs2[1] + rs2[2] + rs2[3];
    float mu  = s  * (1.f/CC);
    float var = s2 * (1.f/CC) - mu*mu;
    float inv = rsqrtf(var + EPSF);
#pragma unroll
    for (int i = 0; i < 3; i++) {
        int c = tid + i*128;
        dst[c] = __float2bfloat16((v[i]-mu)*inv*g[c] + b[c]);
    }
}

// ---------------------------------------------------------------------------
// Kernel 2/5: bf16 tensor-core GEMM  C[16384,384] = A[16384,384] @ W[384,384]
// ---------------------------------------------------------------------------
template<int MODE>
__global__ void __launch_bounds__(256) mma_gemm_kernel(
    const __nv_bfloat16* __restrict__ A,
    const __nv_bfloat16* __restrict__ Bw,
    const float* __restrict__ bias,
    const float* __restrict__ resid,
    const float* __restrict__ gamma,
    float* __restrict__ outF)
{
    __shared__ __nv_bfloat16 As[BM*AS_STRIDE];
    __shared__ __nv_bfloat16 Bs[BKK*BS_STRIDE];

    int tid  = threadIdx.x;
    int warp = tid >> 5, lane = tid & 31;
    int wm = warp >> 1, wn = warp & 1;
    int rowBase = blockIdx.y * BM;
    int colBase = blockIdx.x * BN;

    float acc[2][8][4];
#pragma unroll
    for (int i = 0; i < 2; i++)
#pragma unroll
        for (int j = 0; j < 8; j++)
#pragma unroll
            for (int k = 0; k < 4; k++) acc[i][j][k] = 0.f;

    int a_mrow = (lane & 7) + ((lane >> 3) & 1) * 8;
    int a_kcol = (lane >> 4) * 8;
    int b_krow = (lane & 7) + ((lane >> 3) & 1) * 8;
    int b_ncol = (lane >> 4) * 8;

    for (int kb = 0; kb < CC; kb += BKK) {
#pragma unroll
        for (int i = 0; i < 4; i++) {
            int idx = tid + i*256;
            int r = idx >> 3, c = (idx & 7) * 8;
            *(uint4*)&As[r*AS_STRIDE + c] =
                *(const uint4*)(A + (size_t)(rowBase + r)*CC + kb + c);
        }
#pragma unroll
        for (int i = 0; i < 4; i++) {
            int idx = tid + i*256;
            int r = idx >> 4, c = (idx & 15) * 8;
            *(uint4*)&Bs[r*BS_STRIDE + c] =
                *(const uint4*)(Bw + (size_t)(kb + r)*CC + colBase + c);
        }
        __syncthreads();

#pragma unroll
        for (int ks = 0; ks < 4; ks++) {
            int k0 = ks * 16;
            uint32_t a[2][4];
#pragma unroll
            for (int mf = 0; mf < 2; mf++) {
                int mrow = wm*32 + mf*16 + a_mrow;
                uint32_t addr = (uint32_t)__cvta_generic_to_shared(
                    &As[mrow*AS_STRIDE + k0 + a_kcol]);
                ldm_x4(a[mf][0], a[mf][1], a[mf][2], a[mf][3], addr);
            }
#pragma unroll
            for (int nf4 = 0; nf4 < 4; nf4++) {
                int krow = k0 + b_krow;
                int ncol = wn*64 + nf4*16 + b_ncol;
                uint32_t addr = (uint32_t)__cvta_generic_to_shared(
                    &Bs[krow*BS_STRIDE + ncol]);
                uint32_t b0, b1, b2, b3;
                ldm_x4_trans(b0, b1, b2, b3, addr);
#pragma unroll
                for (int mf = 0; mf < 2; mf++) {
                    mma_bf16(acc[mf][nf4*2 + 0], a[mf], b0, b1);
                    mma_bf16(acc[mf][nf4*2 + 1], a[mf], b2, b3);
                }
            }
        }
        __syncthreads();
    }

    int lrow = lane >> 2;
    int lcol = (lane & 3) * 2;
#pragma unroll
    for (int mf = 0; mf < 2; mf++) {
#pragma unroll
        for (int nf = 0; nf < 8; nf++) {
            int col = colBase + wn*64 + nf*8 + lcol;
            float bx = bias[col], by = bias[col + 1];
#pragma unroll
            for (int half = 0; half < 2; half++) {
                int row = rowBase + wm*32 + mf*16 + lrow + half*8;
                float vx = acc[mf][nf][half*2 + 0] + bx;
                float vy = acc[mf][nf][half*2 + 1] + by;
                if (MODE == 0) {
                    __nv_bfloat162 o;
                    o.x = __float2bfloat16(vx);
                    o.y = __float2bfloat16(vy);
                    *(__nv_bfloat162*)&g_value[(size_t)row*CC + col] = o;
                } else {
                    const float2 rd = *(const float2*)&resid[(size_t)row*CC + col];
                    float2 o;
                    o.x = rd.x + gamma[col]   * vx;
                    o.y = rd.y + gamma[col+1] * vy;
                    *(float2*)&outF[(size_t)row*CC + col] = o;
                }
            }
        }
    }
}

// ---------------------------------------------------------------------------
// Kernel 3: params GEMM [16384x384]@[384x80] on tensor cores + softmax/coords.
// 128 threads = 4 warps; each warp owns 16 rows x 80 cols. BM=64, grid=256.
// ---------------------------------------------------------------------------
__global__ void __launch_bounds__(128) params_mma_kernel(
    const float* __restrict__ bo, const float* __restrict__ ba,
    const float* __restrict__ refp)
{
    __shared__ __nv_bfloat16 As2[PBM*AS_STRIDE];       // 64 x (64+8)
    __shared__ __nv_bfloat16 Ws2[BKK*PW_STRIDE];       // 64 x (80+8)
    __shared__ float         S[PBM][73];

    int tid  = threadIdx.x;
    int warp = tid >> 5, lane = tid & 31;
    int rowBase = blockIdx.x * PBM;

    float acc[10][4];
#pragma unroll
    for (int j = 0; j < 10; j++)
#pragma unroll
        for (int k = 0; k < 4; k++) acc[j][k] = 0.f;

    int a_mrow = (lane & 7) + ((lane >> 3) & 1) * 8;
    int a_kcol = (lane >> 4) * 8;
    int b_krow = (lane & 7) + ((lane >> 3) & 1) * 8;
    int b_ncol = (lane >> 4) * 8;

    for (int kb = 0; kb < CC; kb += BKK) {
        // A tile: 64 x 64 = 512 uint4 over 128 threads
#pragma unroll
        for (int i = 0; i < 4; i++) {
            int idx = tid + i*128;
            int r = idx >> 3, c = (idx & 7) * 8;
            *(uint4*)&As2[r*AS_STRIDE + c] =
                *(const uint4*)(g_qnorm + (size_t)(rowBase + r)*CC + kb + c);
        }
        // W tile: 64 x 80 = 640 uint4 over 128 threads
#pragma unroll
        for (int i = 0; i < 5; i++) {
            int idx = tid + i*128;
            int r = idx / 10, c = (idx % 10) * 8;
            *(uint4*)&Ws2[r*PW_STRIDE + c] =
                *(const uint4*)(g_W72 + (size_t)(kb + r)*PBN + c);
        }
        __syncthreads();

#pragma unroll
        for (int ks = 0; ks < 4; ks++) {
            int k0 = ks * 16;
            uint32_t a[4];
            {
                int mrow = warp*16 + a_mrow;
                uint32_t addr = (uint32_t)__cvta_generic_to_shared(
                    &As2[mrow*AS_STRIDE + k0 + a_kcol]);
                ldm_x4(a[0], a[1], a[2], a[3], addr);
            }
#pragma unroll
            for (int nf4 = 0; nf4 < 5; nf4++) {
                uint32_t addr = (uint32_t)__cvta_generic_to_shared(
                    &Ws2[(k0 + b_krow)*PW_STRIDE + nf4*16 + b_ncol]);
                uint32_t b0, b1, b2, b3;
                ldm_x4_trans(b0, b1, b2, b3, addr);
                mma_bf16(acc[nf4*2 + 0], a, b0, b1);
                mma_bf16(acc[nf4*2 + 1], a, b2, b3);
            }
        }
        __syncthreads();
    }

    // Stage results (cols 0..71) to shared
    int lrow = lane >> 2;
    int lcol = (lane & 3) * 2;
#pragma unroll
    for (int nf = 0; nf < 9; nf++) {       // nf=9 covers cols 72..79 (padding) — skip
        int col = nf*8 + lcol;
#pragma unroll
        for (int half = 0; half < 2; half++) {
            int r = warp*16 + lrow + half*8;
            S[r][col]     = acc[nf][half*2 + 0];
            S[r][col + 1] = acc[nf][half*2 + 1];
        }
    }
    __syncthreads();

    // Postprocess: 64 queries x 6 heads = 384 tasks over 128 threads
#pragma unroll
    for (int i = 0; i < 3; i++) {
        int task = tid + i*128;
        int q = task / 6, h = task % 6;
        int gq = rowBase + q;
        float rx = refp[(size_t)gq*2 + 0] * (float)WLV;
        float ry = refp[(size_t)gq*2 + 1] * (float)HLV;
        float a0 = S[q][48 + h*4 + 0] + ba[h*4 + 0];
        float a1 = S[q][48 + h*4 + 1] + ba[h*4 + 1];
        float a2 = S[q][48 + h*4 + 2] + ba[h*4 + 2];
        float a3 = S[q][48 + h*4 + 3] + ba[h*4 + 3];
        float m  = fmaxf(fmaxf(a0, a1), fmaxf(a2, a3));
        float e0 = expf(a0 - m), e1 = expf(a1 - m), e2 = expf(a2 - m), e3 = expf(a3 - m);
        float inv = 1.f / (e0 + e1 + e2 + e3);
        float ws[4] = {e0*inv, e1*inv, e2*inv, e3*inv};
#pragma unroll
        for (int p = 0; p < 4; p++) {
            float px = rx + S[q][h*8 + 2*p + 0] + bo[h*8 + 2*p + 0] - 0.5f;
            float py = ry + S[q][h*8 + 2*p + 1] + bo[h*8 + 2*p + 1] - 0.5f;
            g_params[(size_t)(gq*NHH + h)*NPP + p] = make_float4(px, py, ws[p], 0.f);
        }
    }
}

// ---------------------------------------------------------------------------
// Kernel 4: bilinear deformable sampling (bf16 value, bf16 out).
// ---------------------------------------------------------------------------
__global__ void __launch_bounds__(384) sample_kernel()
{
    int blk = blockIdx.x;            // 8192 blocks
    int tid = threadIdx.x;
    int sub = tid / 192;
    int t   = tid % 192;
    int gq  = blk*2 + sub;
    int b   = gq >> 12;

    __shared__ float4 prm[2][NHH*NPP];
    if (tid < 2*NHH*NPP)
        prm[tid / 24][tid % 24] = g_params[(size_t)(blk*2)*24 + tid];
    __syncthreads();

    int h  = t >> 5;
    int dp = t & 31;
    const __nv_bfloat16* vb = g_value + (size_t)b*LVN*CC + h*DHH + dp*2;

    float ax = 0.f, ay = 0.f;
#pragma unroll
    for (int p = 0; p < 4; p++) {
        float4 pr = prm[sub][h*NPP + p];
        float x0f = floorf(pr.x), y0f = floorf(pr.y);
        float fx = pr.x - x0f, fy = pr.y - y0f;
        int ix = (int)x0f, iy = (int)y0f;
        float w00 = (1.f-fx)*(1.f-fy)*pr.z;
        float w10 = fx*(1.f-fy)*pr.z;
        float w01 = (1.f-fx)*fy*pr.z;
        float w11 = fx*fy*pr.z;
        bool xv0 = (ix   >= 0) && (ix   < WLV);
        bool xv1 = (ix+1 >= 0) && (ix+1 < WLV);
        if (iy >= 0 && iy < HLV) {
            size_t base = (size_t)iy*WLV*CC;
            if (xv0) {
                float2 f = __bfloat1622float2(*(const __nv_bfloat162*)(vb + base + (size_t)ix*CC));
                ax = fmaf(w00, f.x, ax); ay = fmaf(w00, f.y, ay);
            }
            if (xv1) {
                float2 f = __bfloat1622float2(*(const __nv_bfloat162*)(vb + base + (size_t)(ix+1)*CC));
                ax = fmaf(w10, f.x, ax); ay = fmaf(w10, f.y, ay);
            }
        }
        if (iy+1 >= 0 && iy+1 < HLV) {
            size_t base = (size_t)(iy+1)*WLV*CC;
            if (xv0) {
                float2 f = __bfloat1622float2(*(const __nv_bfloat162*)(vb + base + (size_t)ix*CC));
                ax = fmaf(w01, f.x, ax); ay = fmaf(w01, f.y, ay);
            }
            if (xv1) {
                float2 f = __bfloat1622float2(*(const __nv_bfloat162*)(vb + base + (size_t)(ix+1)*CC));
                ax = fmaf(w11, f.x, ax); ay = fmaf(w11, f.y, ay);
            }
        }
    }
    __nv_bfloat162 o;
    o.x = __float2bfloat16(ax);
    o.y = __float2bfloat16(ay);
    *(__nv_bfloat162*)&g_sampled[(size_t)gq*CC + h*DHH + dp*2] = o;
}

// ---------------------------------------------------------------------------
extern "C" void kernel_launch(void* const* d_in, const int* in_sizes, int n_in,
                              void* d_out, int out_size)
{
    const float* query = (const float*)d_in[0];
    const float* refp  = (const float*)d_in[1];
    const float* feat  = (const float*)d_in[2];
    const float* ln_q_g = (const float*)d_in[5];
    const float* ln_q_b = (const float*)d_in[6];
    const float* ln_f_g = (const float*)d_in[7];
    const float* ln_f_b = (const float*)d_in[8];
    const float* gamma  = (const float*)d_in[9];
    const float* Wv   = (const float*)d_in[10];
    const float* bv   = (const float*)d_in[11];
    const float* Wo   = (const float*)d_in[12];
    const float* bo   = (const float*)d_in[13];
    const float* Wa   = (const float*)d_in[14];
    const float* ba   = (const float*)d_in[15];
    const float* Wout = (const float*)d_in[16];
    const float* bout = (const float*)d_in[17];
    float* out = (float*)d_out;

    __nv_bfloat16 *p_fnorm, *p_sampled, *p_Wv, *p_Wout;
    cudaGetSymbolAddress((void**)&p_fnorm,   g_fnorm);
    cudaGetSymbolAddress((void**)&p_sampled, g_sampled);
    cudaGetSymbolAddress((void**)&p_Wv,      g_Wv_bf);
    cudaGetSymbolAddress((void**)&p_Wout,    g_Wout_bf);

    // 0. weights -> bf16 (incl. packed [Wo|Wa|0])
    convert_w_kernel<<<(CC*CC + 255)/256, 256>>>(Wv, Wout, Wo, Wa);

    // 1. LayerNorms (both -> bf16)
    ln_kernel<<<2*NROWS, 128>>>(feat, query, ln_f_g, ln_f_b, ln_q_g, ln_q_b);

    // 2. value = f_norm @ Wv + bv   (bf16 out)
    mma_gemm_kernel<0><<<dim3(CC/BN, NROWS/BM), 256>>>(
        p_fnorm, p_Wv, bv, nullptr, nullptr, nullptr);

    // 3. sampling params (tensor-core GEMM + softmax + coords)
    params_mma_kernel<<<NROWS/PBM, 128>>>(bo, ba, refp);

    // 4. bilinear sampling (bf16 in/out)
    sample_kernel<<<NROWS/2, 384>>>();

    // 5. out = query + gamma * (sampled @ Wout + bout)
    mma_gemm_kernel<1><<<dim3(CC/BN, NROWS/BM), 256>>>(
        p_sampled, p_Wout, bout, query, gamma, out);
}